// round 15
// baseline (speedup 1.0000x reference)
#include <cuda_runtime.h>
#include <cuda_fp16.h>
#include <cstdint>

// Problem constants (fixed shapes)
#define BB 8
#define GG 64
#define CC 192
#define HWN 65536          // H*W
#define OO 256             // width2

#define WPITCH 72          // fp16 elements per row (144B): conflict-free ldmatrix
#define YELEMS (64 * WPITCH)              // halfs per Y buffer
#define SMEM_W_BYTES (OO * WPITCH * 2)    // 36864
#define SMEM_TOTAL (SMEM_W_BYTES + 2 * YELEMS * 2)   // 55296

#define N_TILES 8192       // (b, n0) tiles of 64 n
#define GRID_FUSED 296     // 2 resident CTAs per SM, single wave, stride sched

#define N_ITEMS 512        // (b,g) attention items
#define QSPLIT 4           // quarters per item
#define GRID_ATTN (N_ITEMS * QSPLIT)

// ---------------------------------------------------------------------------
// Device scratch
// ---------------------------------------------------------------------------
__device__ float4 g_attnW[BB * GG];
__device__ __align__(16) __half g_Whalf[OO * WPITCH];
__device__ float2 g_bn2[OO];
__device__ float g_part[N_ITEMS * QSPLIT * 9];   // partial Gram sums
__device__ unsigned g_sync[N_ITEMS + 1];         // [0..511] item counters, [512] prep

__device__ __forceinline__ uint32_t smem_u32(const void* p) {
    uint32_t a;
    asm("{ .reg .u64 t; cvta.to.shared.u64 t, %1; cvt.u32.u64 %0, t; }" : "=r"(a) : "l"(p));
    return a;
}
__device__ __forceinline__ void ldmat_x4(uint32_t* r, uint32_t addr) {
    asm volatile("ldmatrix.sync.aligned.m8n8.x4.shared.b16 {%0,%1,%2,%3}, [%4];"
                 : "=r"(r[0]), "=r"(r[1]), "=r"(r[2]), "=r"(r[3]) : "r"(addr));
}
__device__ __forceinline__ void ldmat_x4_trans(uint32_t* r, uint32_t addr) {
    asm volatile("ldmatrix.sync.aligned.m8n8.x4.trans.shared.b16 {%0,%1,%2,%3}, [%4];"
                 : "=r"(r[0]), "=r"(r[1]), "=r"(r[2]), "=r"(r[3]) : "r"(addr));
}
__device__ __forceinline__ void mma_16816(float* d, const uint32_t* a, const uint32_t* b) {
    asm volatile("mma.sync.aligned.m16n8k16.row.col.f32.f16.f16.f32 "
                 "{%0,%1,%2,%3}, {%4,%5,%6,%7}, {%8,%9}, {%0,%1,%2,%3};"
                 : "+f"(d[0]), "+f"(d[1]), "+f"(d[2]), "+f"(d[3])
                 : "r"(a[0]), "r"(a[1]), "r"(a[2]), "r"(a[3]), "r"(b[0]), "r"(b[1]));
}

// ---------------------------------------------------------------------------
// Kernel 1: attention statistics, 4-way split per (b,g) item.
// 2048 CTAs of 256 threads; quarter-partials combined by last-arriving CTA
// in fixed order (deterministic). Blocks 0..63 also do the prep slice.
// ---------------------------------------------------------------------------
__global__ __launch_bounds__(256) void attn_kernel(
    const float* __restrict__ x,
    const float* __restrict__ aw,
    const float* __restrict__ bn1_g, const float* __restrict__ bn1_b,
    const float* __restrict__ bn1_m, const float* __restrict__ bn1_v,
    const float* __restrict__ convw,
    const float* __restrict__ bn2_g, const float* __restrict__ bn2_b,
    const float* __restrict__ bn2_m, const float* __restrict__ bn2_v)
{
    const int cta  = blockIdx.x;           // 0..2047
    const int item = cta >> 2;             // b*64 + g
    const int q    = cta & 3;
    const int g    = item & 63;
    const float* xb = x + (size_t)item * 3 * HWN;

    const int t    = threadIdx.x;
    const int lane = t & 31;
    const int warp = t >> 5;

    // ---- inlined prep (first 64 blocks) ----
    if (cta < 64) {
        const int i = cta * 256 + t;       // 0..16383
        const int k = i & 63;
        const int o = i >> 6;
        g_Whalf[o * WPITCH + k] = __float2half(convw[o * GG + k]);
        if (i < OO) {
#pragma unroll
            for (int z = 64; z < WPITCH; z++)
                g_Whalf[i * WPITCH + z] = __float2half(0.f);
            float sc = bn2_g[i] * rsqrtf(bn2_v[i] + 1e-5f);
            float bi = bn2_b[i] - sc * bn2_m[i];
            g_bn2[i] = make_float2(sc, bi);
        }
        __syncthreads();
        if (t == 0) {
            __threadfence();
            atomicAdd(&g_sync[N_ITEMS], 1u);
        }
    }

    // allow dependent (fused) kernel CTAs to launch as resources free up
    cudaTriggerProgrammaticLaunchCompletion();

    float acc[9];
#pragma unroll
    for (int z = 0; z < 9; z++) acc[z] = 0.0f;

    // quarter q: windows [q*1024, q*1024+1024)
#pragma unroll 1
    for (int it = 0; it < 4; it++) {
        const int wIdx = q * 1024 + it * 256 + t;
        const int wy = wIdx >> 6;
        const int wx = wIdx & 63;
        float m[3], s[3];
#pragma unroll
        for (int ch = 0; ch < 3; ch++) {
            const float4* pc = (const float4*)(xb + (size_t)ch * HWN + (wy * 4) * 256 + wx * 4);
            float4 r0 = __ldcs(pc);
            float4 r1 = __ldcs(pc + 64);
            float4 r2 = __ldcs(pc + 128);
            float4 r3 = __ldcs(pc + 192);
            float mx = fmaxf(fmaxf(fmaxf(r0.x, r0.y), fmaxf(r0.z, r0.w)),
                      fmaxf(fmaxf(fmaxf(r1.x, r1.y), fmaxf(r1.z, r1.w)),
                      fmaxf(fmaxf(fmaxf(r2.x, r2.y), fmaxf(r2.z, r2.w)),
                            fmaxf(fmaxf(r3.x, r3.y), fmaxf(r3.z, r3.w)))));
            float sm = (r0.x + r0.y + r0.z + r0.w) + (r1.x + r1.y + r1.z + r1.w)
                     + (r2.x + r2.y + r2.z + r2.w) + (r3.x + r3.y + r3.z + r3.w);
            m[ch] = mx;
            s[ch] = sm;
        }
#pragma unroll
        for (int i = 0; i < 3; i++)
#pragma unroll
            for (int j = 0; j < 3; j++)
                acc[i * 3 + j] += m[i] * s[j];
    }

    __shared__ float red[9][8];
    __shared__ float fin[9];
#pragma unroll
    for (int z = 0; z < 9; z++) {
        float v = acc[z];
#pragma unroll
        for (int off = 16; off > 0; off >>= 1)
            v += __shfl_xor_sync(0xFFFFFFFFu, v, off);
        if (lane == 0) red[z][warp] = v;
    }
    __syncthreads();
    if (t < 9) {
        float s = 0.0f;
#pragma unroll
        for (int w = 0; w < 8; w++) s += red[t][w];
        fin[t] = s;
        // publish quarter partial
        g_part[(item * QSPLIT + q) * 9 + t] = s;
        __threadfence();
    }
    __syncthreads();

    if (t == 0) {
        if (atomicAdd(&g_sync[item], 1u) == QSPLIT - 1) {
            __threadfence();
            // deterministic fixed-order combine of the 4 quarter partials
            const float* pp = g_part + item * QSPLIT * 9;
            float tot[9];
#pragma unroll
            for (int z = 0; z < 9; z++)
                tot[z] = __ldcg(pp + z) + __ldcg(pp + 9 + z)
                       + __ldcg(pp + 18 + z) + __ldcg(pp + 27 + z);
            const float w0 = aw[g * 3 + 0], w1 = aw[g * 3 + 1], w2 = aw[g * 3 + 2];
            float r0 = (tot[0] * w0 + tot[3] * w1 + tot[6] * w2) * (1.0f / 1024.0f);
            float r1 = (tot[1] * w0 + tot[4] * w1 + tot[7] * w2) * (1.0f / 1024.0f);
            float r2 = (tot[2] * w0 + tot[5] * w1 + tot[8] * w2) * (1.0f / 1024.0f);
            float mx = fmaxf(r0, fmaxf(r1, r2));
            float e0 = __expf(r0 - mx), e1 = __expf(r1 - mx), e2 = __expf(r2 - mx);
            float inv = 1.0f / (e0 + e1 + e2);
            float sc = bn1_g[g] * rsqrtf(bn1_v[g] + 1e-5f);
            float cc = bn1_b[g] - sc * bn1_m[g];
            float4 o;
            o.x = sc * e0 * inv;
            o.y = sc * e1 * inv;
            o.z = sc * e2 * inv;
            o.w = cc;
            g_attnW[item] = o;
        }
    }
}

// ---------------------------------------------------------------------------
// Kernel 2: persistent fused kernel (PDL secondary). Best-known config:
// stride scheduling, double-buffered Ysm, 12-batched Phase-A LDG.128,
// W-copy overlapped with attn drain (gated on prep slice).
// ---------------------------------------------------------------------------
__global__ __launch_bounds__(256, 2) void fused_kernel(
    const float* __restrict__ x,
    float* __restrict__ out)
{
    extern __shared__ __align__(16) char smem[];
    __half* Wsm = (__half*)smem;                          // [o][k] pitch 72
    __half* Ybuf = (__half*)(smem + SMEM_W_BYTES);        // 2 x [k][n] pitch 72

    const int t    = threadIdx.x;
    const int lane = t & 31;
    const int wid  = t >> 5;

    // ---- gate on prep slice, then W copy (overlaps attn's tail) ----
    if (t == 0) {
        while (atomicAdd(&g_sync[N_ITEMS], 0u) < 64u) __nanosleep(64);
    }
    __syncthreads();
    {
        const float4* src = (const float4*)g_Whalf;
        float4* dst = (float4*)Wsm;
#pragma unroll
        for (int i = 0; i < 9; i++) {
            float4 v;
            asm volatile("ld.global.cg.v4.f32 {%0,%1,%2,%3}, [%4];"
                         : "=f"(v.x), "=f"(v.y), "=f"(v.z), "=f"(v.w)
                         : "l"(src + i * 256 + t));
            dst[i * 256 + t] = v;
        }
    }

    // Tile-invariant addressing
    const int ow = (wid >> 1) * 64;
    const int nw = (wid & 1) * 32;
    const uint32_t wbase = smem_u32(Wsm);
    const uint32_t ybase = smem_u32(Ybuf);
    const uint32_t aAddr = wbase + (ow + (lane & 15)) * (WPITCH * 2) + ((lane >> 4) * 8) * 2;
    const uint32_t brow = ((lane >> 3) & 1) * 8 + (lane & 7);
    const uint32_t bcol = nw + ((lane >> 4) * 8);
    const uint32_t bAddr0 = ybase + brow * (WPITCH * 2) + bcol * 2;
    const int gi   = t >> 4;            // 0..15
    const int pos4 = (t & 15) * 4;

    // ---- wait for the attn grid to fully complete (attnW ready) ----
    cudaGridDependencySynchronize();

    int p = 0;
#pragma unroll 1
    for (int tile = blockIdx.x; tile < N_TILES; tile += GRID_FUSED) {
        const int b  = tile >> 10;
        const int n0 = (tile & 1023) << 6;
        __half* Ysm = Ybuf + p * YELEMS;

        // ---- Phase A: Y = relu(bn1(sum_j a_j x_j)) -> fp16 smem [k][n] ----
        {
            const float* xb = x + (size_t)b * CC * HWN + n0 + pos4;
            const float4* awb = g_attnW + b * GG;
            float4 a[4];
            float4 xv[4][3];
#pragma unroll
            for (int u = 0; u < 4; u++) {
                const int g = u * 16 + gi;
                a[u] = __ldg(awb + g);
                const float* pg = xb + (size_t)(g * 3) * HWN;
                xv[u][0] = __ldcs((const float4*)pg);
                xv[u][1] = __ldcs((const float4*)(pg + HWN));
                xv[u][2] = __ldcs((const float4*)(pg + 2 * HWN));
            }
#pragma unroll
            for (int u = 0; u < 4; u++) {
                const int g = u * 16 + gi;
                float y0 = fmaxf(fmaf(a[u].x, xv[u][0].x, fmaf(a[u].y, xv[u][1].x, fmaf(a[u].z, xv[u][2].x, a[u].w))), 0.0f);
                float y1 = fmaxf(fmaf(a[u].x, xv[u][0].y, fmaf(a[u].y, xv[u][1].y, fmaf(a[u].z, xv[u][2].y, a[u].w))), 0.0f);
                float y2 = fmaxf(fmaf(a[u].x, xv[u][0].z, fmaf(a[u].y, xv[u][1].z, fmaf(a[u].z, xv[u][2].z, a[u].w))), 0.0f);
                float y3 = fmaxf(fmaf(a[u].x, xv[u][0].w, fmaf(a[u].y, xv[u][1].w, fmaf(a[u].z, xv[u][2].w, a[u].w))), 0.0f);
                union { __half2 h[2]; uint2 uu; } pk;
                pk.h[0] = __floats2half2_rn(y0, y1);
                pk.h[1] = __floats2half2_rn(y2, y3);
                *(uint2*)(Ysm + g * WPITCH + pos4) = pk.uu;
            }
        }
        __syncthreads();    // the only barrier per tile: A(p) ready for B(p)

        // ---- Phase B: HMMA GEMM (reads buffer p) ----
        float acc[4][4][4];
#pragma unroll
        for (int m = 0; m < 4; m++)
#pragma unroll
            for (int j = 0; j < 4; j++)
#pragma unroll
                for (int q = 0; q < 4; q++) acc[m][j][q] = 0.0f;

        const uint32_t bAddr = bAddr0 + p * (YELEMS * 2);

#pragma unroll
        for (int k0 = 0; k0 < 64; k0 += 16) {
            uint32_t afr[4][4];
#pragma unroll
            for (int m = 0; m < 4; m++)
                ldmat_x4(afr[m], aAddr + m * 16 * (WPITCH * 2) + k0 * 2);
            uint32_t bq0[4], bq1[4];
            ldmat_x4_trans(bq0, bAddr + k0 * (WPITCH * 2));
            ldmat_x4_trans(bq1, bAddr + k0 * (WPITCH * 2) + 16 * 2);
            const uint32_t* bfr[4] = { &bq0[0], &bq0[2], &bq1[0], &bq1[2] };
#pragma unroll
            for (int m = 0; m < 4; m++)
#pragma unroll
                for (int j = 0; j < 4; j++)
                    mma_16816(acc[m][j], afr[m], bfr[j]);
        }

        // ---- Epilogue: bn2 + store ----
        {
            const int ncol = n0 + nw + (lane & 3) * 2;
#pragma unroll
            for (int m = 0; m < 4; m++) {
                const int r0 = ow + m * 16 + (lane >> 2);
                const int r1 = r0 + 8;
                const float2 s0 = __ldg(&g_bn2[r0]);
                const float2 s1 = __ldg(&g_bn2[r1]);
                float* p0 = out + ((size_t)(b * OO + r0)) * HWN + ncol;
                float* p1 = out + ((size_t)(b * OO + r1)) * HWN + ncol;
#pragma unroll
                for (int j = 0; j < 4; j++) {
                    float2 v0, v1;
                    v0.x = fmaf(acc[m][j][0], s0.x, s0.y);
                    v0.y = fmaf(acc[m][j][1], s0.x, s0.y);
                    v1.x = fmaf(acc[m][j][2], s1.x, s1.y);
                    v1.y = fmaf(acc[m][j][3], s1.x, s1.y);
                    *(float2*)(p0 + j * 8) = v0;
                    *(float2*)(p1 + j * 8) = v1;
                }
            }
        }
        p ^= 1;
    }
}

extern "C" void kernel_launch(void* const* d_in, const int* in_sizes, int n_in,
                              void* d_out, int out_size)
{
    const float* x     = (const float*)d_in[0];
    const float* aw    = (const float*)d_in[1];
    const float* bn1_g = (const float*)d_in[2];
    const float* bn1_b = (const float*)d_in[3];
    const float* bn1_m = (const float*)d_in[4];
    const float* bn1_v = (const float*)d_in[5];
    const float* convw = (const float*)d_in[6];
    const float* bn2_g = (const float*)d_in[7];
    const float* bn2_b = (const float*)d_in[8];
    const float* bn2_m = (const float*)d_in[9];
    const float* bn2_v = (const float*)d_in[10];
    float* out = (float*)d_out;

    cudaFuncSetAttribute(fused_kernel, cudaFuncAttributeMaxDynamicSharedMemorySize, SMEM_TOTAL);

    // reset per-replay flags (graph-capturable memset node; no allocation)
    void* flags = nullptr;
    cudaGetSymbolAddress(&flags, g_sync);
    cudaMemsetAsync(flags, 0, sizeof(unsigned) * (N_ITEMS + 1), 0);

    attn_kernel<<<GRID_ATTN, 256>>>(x, aw, bn1_g, bn1_b, bn1_m, bn1_v,
                                    convw, bn2_g, bn2_b, bn2_m, bn2_v);

    // fused kernel as PDL secondary: CTAs may launch while attn drains
    cudaLaunchConfig_t cfg = {};
    cfg.gridDim = dim3(GRID_FUSED, 1, 1);
    cfg.blockDim = dim3(256, 1, 1);
    cfg.dynamicSmemBytes = SMEM_TOTAL;
    cfg.stream = 0;
    cudaLaunchAttribute attrs[1];
    attrs[0].id = cudaLaunchAttributeProgrammaticStreamSerialization;
    attrs[0].val.programmaticStreamSerializationAllowed = 1;
    cfg.attrs = attrs;
    cfg.numAttrs = 1;
    cudaLaunchKernelEx(&cfg, fused_kernel, x, out);
}

// round 16
// speedup vs baseline: 1.0193x; 1.0193x over previous
#include <cuda_runtime.h>
#include <cuda_fp16.h>
#include <cstdint>

// Problem constants (fixed shapes)
#define BB 8
#define GG 64
#define CC 192
#define HWN 65536          // H*W
#define OO 256             // width2

#define WPITCH 72          // fp16 elements per row (144B): conflict-free ldmatrix
#define YELEMS (64 * WPITCH)              // halfs per Y buffer
#define SMEM_W_BYTES (OO * WPITCH * 2)    // 36864 (W staging, prologue only)
// Y double buffer (2 x 9216 B) aliases the W staging region after the
// one-time A-fragment hoist. Total = W staging size.
#define SMEM_TOTAL SMEM_W_BYTES

#define N_TILES 8192       // (b, n0) tiles of 64 n
#define GRID_FUSED 296     // 2 resident CTAs per SM, single wave, stride sched

// ---------------------------------------------------------------------------
// Device scratch
// ---------------------------------------------------------------------------
__device__ float4 g_attnW[BB * GG];
__device__ __align__(16) __half g_Whalf[OO * WPITCH];
__device__ float2 g_bn2[OO];
__device__ unsigned g_prep = 0;    // prep-slice completion counter (reset by fused)

__device__ __forceinline__ uint32_t smem_u32(const void* p) {
    uint32_t a;
    asm("{ .reg .u64 t; cvta.to.shared.u64 t, %1; cvt.u32.u64 %0, t; }" : "=r"(a) : "l"(p));
    return a;
}
__device__ __forceinline__ void ldmat_x4(uint32_t* r, uint32_t addr) {
    asm volatile("ldmatrix.sync.aligned.m8n8.x4.shared.b16 {%0,%1,%2,%3}, [%4];"
                 : "=r"(r[0]), "=r"(r[1]), "=r"(r[2]), "=r"(r[3]) : "r"(addr));
}
__device__ __forceinline__ void ldmat_x4_trans(uint32_t* r, uint32_t addr) {
    asm volatile("ldmatrix.sync.aligned.m8n8.x4.trans.shared.b16 {%0,%1,%2,%3}, [%4];"
                 : "=r"(r[0]), "=r"(r[1]), "=r"(r[2]), "=r"(r[3]) : "r"(addr));
}
__device__ __forceinline__ void mma_16816(float* d, const uint32_t* a, const uint32_t* b) {
    asm volatile("mma.sync.aligned.m16n8k16.row.col.f32.f16.f16.f32 "
                 "{%0,%1,%2,%3}, {%4,%5,%6,%7}, {%8,%9}, {%0,%1,%2,%3};"
                 : "+f"(d[0]), "+f"(d[1]), "+f"(d[2]), "+f"(d[3])
                 : "r"(a[0]), "r"(a[1]), "r"(a[2]), "r"(a[3]), "r"(b[0]), "r"(b[1]));
}

// ---------------------------------------------------------------------------
// Kernel 1: attention statistics + (blocks 0..63) inlined prep (R14 form).
// ---------------------------------------------------------------------------
__global__ __launch_bounds__(256) void attn_kernel(
    const float* __restrict__ x,
    const float* __restrict__ aw,
    const float* __restrict__ bn1_g, const float* __restrict__ bn1_b,
    const float* __restrict__ bn1_m, const float* __restrict__ bn1_v,
    const float* __restrict__ convw,
    const float* __restrict__ bn2_g, const float* __restrict__ bn2_b,
    const float* __restrict__ bn2_m, const float* __restrict__ bn2_v)
{
    const int bg = blockIdx.x;
    const int g  = bg & 63;
    const float* xb = x + (size_t)bg * 3 * HWN;

    const int t    = threadIdx.x;
    const int lane = t & 31;
    const int warp = t >> 5;

    // ---- inlined prep (first 64 blocks) ----
    if (bg < 64) {
        const int i = bg * 256 + t;        // 0..16383
        const int k = i & 63;
        const int o = i >> 6;
        g_Whalf[o * WPITCH + k] = __float2half(convw[o * GG + k]);
        if (i < OO) {
#pragma unroll
            for (int z = 64; z < WPITCH; z++)
                g_Whalf[i * WPITCH + z] = __float2half(0.f);
            float sc = bn2_g[i] * rsqrtf(bn2_v[i] + 1e-5f);
            float bi = bn2_b[i] - sc * bn2_m[i];
            g_bn2[i] = make_float2(sc, bi);
        }
        __syncthreads();
        if (t == 0) {
            __threadfence();
            atomicAdd(&g_prep, 1u);
        }
    }

    // allow dependent (fused) kernel CTAs to launch as resources free up
    cudaTriggerProgrammaticLaunchCompletion();

    float acc[9];
#pragma unroll
    for (int q = 0; q < 9; q++) acc[q] = 0.0f;

#pragma unroll 1
    for (int it = 0; it < 16; it++) {
        const int wIdx = it * 256 + t;
        const int wy = wIdx >> 6;
        const int wx = wIdx & 63;
        float m[3], s[3];
#pragma unroll
        for (int ch = 0; ch < 3; ch++) {
            const float4* pc = (const float4*)(xb + (size_t)ch * HWN + (wy * 4) * 256 + wx * 4);
            float4 r0 = __ldcs(pc);
            float4 r1 = __ldcs(pc + 64);
            float4 r2 = __ldcs(pc + 128);
            float4 r3 = __ldcs(pc + 192);
            float mx = fmaxf(fmaxf(fmaxf(r0.x, r0.y), fmaxf(r0.z, r0.w)),
                      fmaxf(fmaxf(fmaxf(r1.x, r1.y), fmaxf(r1.z, r1.w)),
                      fmaxf(fmaxf(fmaxf(r2.x, r2.y), fmaxf(r2.z, r2.w)),
                            fmaxf(fmaxf(r3.x, r3.y), fmaxf(r3.z, r3.w)))));
            float sm = (r0.x + r0.y + r0.z + r0.w) + (r1.x + r1.y + r1.z + r1.w)
                     + (r2.x + r2.y + r2.z + r2.w) + (r3.x + r3.y + r3.z + r3.w);
            m[ch] = mx;
            s[ch] = sm;
        }
#pragma unroll
        for (int i = 0; i < 3; i++)
#pragma unroll
            for (int j = 0; j < 3; j++)
                acc[i * 3 + j] += m[i] * s[j];
    }

    __shared__ float red[9][8];
    __shared__ float fin[9];
#pragma unroll
    for (int q = 0; q < 9; q++) {
        float v = acc[q];
#pragma unroll
        for (int off = 16; off > 0; off >>= 1)
            v += __shfl_xor_sync(0xFFFFFFFFu, v, off);
        if (lane == 0) red[q][warp] = v;
    }
    __syncthreads();
    if (t < 9) {
        float s = 0.0f;
#pragma unroll
        for (int w = 0; w < 8; w++) s += red[t][w];
        fin[t] = s;
    }
    __syncthreads();

    if (t == 0) {
        const float w0 = aw[g * 3 + 0], w1 = aw[g * 3 + 1], w2 = aw[g * 3 + 2];
        float r0 = (fin[0] * w0 + fin[3] * w1 + fin[6] * w2) * (1.0f / 1024.0f);
        float r1 = (fin[1] * w0 + fin[4] * w1 + fin[7] * w2) * (1.0f / 1024.0f);
        float r2 = (fin[2] * w0 + fin[5] * w1 + fin[8] * w2) * (1.0f / 1024.0f);
        float mx = fmaxf(r0, fmaxf(r1, r2));
        float e0 = __expf(r0 - mx), e1 = __expf(r1 - mx), e2 = __expf(r2 - mx);
        float inv = 1.0f / (e0 + e1 + e2);
        float sc = bn1_g[g] * rsqrtf(bn1_v[g] + 1e-5f);
        float cc = bn1_b[g] - sc * bn1_m[g];
        float4 o;
        o.x = sc * e0 * inv;
        o.y = sc * e1 * inv;
        o.z = sc * e2 * inv;
        o.w = cc;
        g_attnW[bg] = o;
    }
}

// ---------------------------------------------------------------------------
// Kernel 2: persistent fused kernel (PDL secondary).
// NEW: warp tile 32o x 64n; A (W) fragments hoisted into registers ONCE per
// CTA (zero A-ldmatrix in the tile loop); W smem staging aliased with the
// Y double buffer (smem 36.9KB/CTA).
// ---------------------------------------------------------------------------
__global__ __launch_bounds__(256, 2) void fused_kernel(
    const float* __restrict__ x,
    float* __restrict__ out)
{
    extern __shared__ __align__(16) char smem[];
    __half* Wstage = (__half*)smem;               // prologue only
    __half* Ybuf   = (__half*)smem;               // aliases Wstage after hoist

    const int t    = threadIdx.x;
    const int lane = t & 31;
    const int wid  = t >> 5;

    // ---- gate on prep slice, then W copy (overlaps attn's tail) ----
    if (t == 0) {
        while (atomicAdd(&g_prep, 0u) < 64u) __nanosleep(64);
    }
    __syncthreads();
    {
        const float4* src = (const float4*)g_Whalf;
        float4* dst = (float4*)Wstage;
#pragma unroll
        for (int i = 0; i < 9; i++) {
            float4 v;
            asm volatile("ld.global.cg.v4.f32 {%0,%1,%2,%3}, [%4];"
                         : "=f"(v.x), "=f"(v.y), "=f"(v.z), "=f"(v.w)
                         : "l"(src + i * 256 + t));
            dst[i * 256 + t] = v;
        }
    }
    __syncthreads();

    // ---- one-time A-fragment hoist: rows [ow, ow+32), all K=64 ----
    const int ow = wid * 32;
    uint32_t afr[4][2][4];       // [ks][m][frag] = 32 regs, permanent
    {
        const uint32_t wbase = smem_u32(Wstage);
        const uint32_t aAddr = wbase + (ow + (lane & 15)) * (WPITCH * 2) + ((lane >> 4) * 8) * 2;
#pragma unroll
        for (int ks = 0; ks < 4; ks++)
#pragma unroll
            for (int m = 0; m < 2; m++)
                ldmat_x4(afr[ks][m], aAddr + m * 16 * (WPITCH * 2) + ks * 16 * 2);
    }
    __syncthreads();   // all warps done reading Wstage; Ybuf may overwrite it

    // Tile-invariant addressing
    const uint32_t ybase = smem_u32(Ybuf);
    const uint32_t brow = ((lane >> 3) & 1) * 8 + (lane & 7);
    const uint32_t bAddr0 = ybase + brow * (WPITCH * 2) + ((lane >> 4) * 8) * 2;
    const int gi   = t >> 4;            // 0..15
    const int pos4 = (t & 15) * 4;

    // ---- wait for the attn grid to fully complete (attnW ready) ----
    cudaGridDependencySynchronize();

    int p = 0;
#pragma unroll 1
    for (int tile = blockIdx.x; tile < N_TILES; tile += GRID_FUSED) {
        const int b  = tile >> 10;
        const int n0 = (tile & 1023) << 6;
        __half* Ysm = Ybuf + p * YELEMS;

        // ---- Phase A: Y = relu(bn1(sum_j a_j x_j)) -> fp16 smem [k][n] ----
        {
            const float* xb = x + (size_t)b * CC * HWN + n0 + pos4;
            const float4* awb = g_attnW + b * GG;
            float4 a[4];
            float4 xv[4][3];
#pragma unroll
            for (int u = 0; u < 4; u++) {
                const int g = u * 16 + gi;
                a[u] = __ldg(awb + g);
                const float* pg = xb + (size_t)(g * 3) * HWN;
                xv[u][0] = __ldcs((const float4*)pg);
                xv[u][1] = __ldcs((const float4*)(pg + HWN));
                xv[u][2] = __ldcs((const float4*)(pg + 2 * HWN));
            }
#pragma unroll
            for (int u = 0; u < 4; u++) {
                const int g = u * 16 + gi;
                float y0 = fmaxf(fmaf(a[u].x, xv[u][0].x, fmaf(a[u].y, xv[u][1].x, fmaf(a[u].z, xv[u][2].x, a[u].w))), 0.0f);
                float y1 = fmaxf(fmaf(a[u].x, xv[u][0].y, fmaf(a[u].y, xv[u][1].y, fmaf(a[u].z, xv[u][2].y, a[u].w))), 0.0f);
                float y2 = fmaxf(fmaf(a[u].x, xv[u][0].z, fmaf(a[u].y, xv[u][1].z, fmaf(a[u].z, xv[u][2].z, a[u].w))), 0.0f);
                float y3 = fmaxf(fmaf(a[u].x, xv[u][0].w, fmaf(a[u].y, xv[u][1].w, fmaf(a[u].z, xv[u][2].w, a[u].w))), 0.0f);
                union { __half2 h[2]; uint2 uu; } pk;
                pk.h[0] = __floats2half2_rn(y0, y1);
                pk.h[1] = __floats2half2_rn(y2, y3);
                *(uint2*)(Ysm + g * WPITCH + pos4) = pk.uu;
            }
        }
        __syncthreads();    // A(p) ready for B(p); also orders prev B reads

        // ---- Phase B: HMMA GEMM, warp = 32o x 64n, A from registers ----
        float acc[2][8][4];
#pragma unroll
        for (int m = 0; m < 2; m++)
#pragma unroll
            for (int j = 0; j < 8; j++)
#pragma unroll
                for (int q = 0; q < 4; q++) acc[m][j][q] = 0.0f;

        const uint32_t bAddr = bAddr0 + p * (YELEMS * 2);

#pragma unroll
        for (int ks = 0; ks < 4; ks++) {
            uint32_t bq[4][4];     // n-blocks {0,1},{2,3},{4,5},{6,7}
#pragma unroll
            for (int c = 0; c < 4; c++)
                ldmat_x4_trans(bq[c], bAddr + ks * 16 * (WPITCH * 2) + c * 16 * 2);
#pragma unroll
            for (int m = 0; m < 2; m++)
#pragma unroll
                for (int j = 0; j < 8; j++)
                    mma_16816(acc[m][j], afr[ks][m], &bq[j >> 1][(j & 1) * 2]);
        }

        // ---- Epilogue: bn2 + store ----
        {
            const int ncol = n0 + (lane & 3) * 2;
#pragma unroll
            for (int m = 0; m < 2; m++) {
                const int r0 = ow + m * 16 + (lane >> 2);
                const int r1 = r0 + 8;
                const float2 s0 = __ldg(&g_bn2[r0]);
                const float2 s1 = __ldg(&g_bn2[r1]);
                float* p0 = out + ((size_t)(b * OO + r0)) * HWN + ncol;
                float* p1 = out + ((size_t)(b * OO + r1)) * HWN + ncol;
#pragma unroll
                for (int j = 0; j < 8; j++) {
                    float2 v0, v1;
                    v0.x = fmaf(acc[m][j][0], s0.x, s0.y);
                    v0.y = fmaf(acc[m][j][1], s0.x, s0.y);
                    v1.x = fmaf(acc[m][j][2], s1.x, s1.y);
                    v1.y = fmaf(acc[m][j][3], s1.x, s1.y);
                    *(float2*)(p0 + j * 8) = v0;
                    *(float2*)(p1 + j * 8) = v1;
                }
            }
        }
        p ^= 1;
    }

    // reset prep counter for the next graph replay (all CTAs passed the gate
    // within their prologue, long before CTA 0 retires)
    if (blockIdx.x == 0 && t == 0) g_prep = 0;
}

extern "C" void kernel_launch(void* const* d_in, const int* in_sizes, int n_in,
                              void* d_out, int out_size)
{
    const float* x     = (const float*)d_in[0];
    const float* aw    = (const float*)d_in[1];
    const float* bn1_g = (const float*)d_in[2];
    const float* bn1_b = (const float*)d_in[3];
    const float* bn1_m = (const float*)d_in[4];
    const float* bn1_v = (const float*)d_in[5];
    const float* convw = (const float*)d_in[6];
    const float* bn2_g = (const float*)d_in[7];
    const float* bn2_b = (const float*)d_in[8];
    const float* bn2_m = (const float*)d_in[9];
    const float* bn2_v = (const float*)d_in[10];
    float* out = (float*)d_out;

    cudaFuncSetAttribute(fused_kernel, cudaFuncAttributeMaxDynamicSharedMemorySize, SMEM_TOTAL);

    attn_kernel<<<BB * GG, 256>>>(x, aw, bn1_g, bn1_b, bn1_m, bn1_v,
                                  convw, bn2_g, bn2_b, bn2_m, bn2_v);

    // fused kernel as PDL secondary: CTAs may launch while attn drains
    cudaLaunchConfig_t cfg = {};
    cfg.gridDim = dim3(GRID_FUSED, 1, 1);
    cfg.blockDim = dim3(256, 1, 1);
    cfg.dynamicSmemBytes = SMEM_TOTAL;
    cfg.stream = 0;
    cudaLaunchAttribute attrs[1];
    attrs[0].id = cudaLaunchAttributeProgrammaticStreamSerialization;
    attrs[0].val.programmaticStreamSerializationAllowed = 1;
    cfg.attrs = attrs;
    cfg.numAttrs = 1;
    cudaLaunchKernelEx(&cfg, fused_kernel, x, out);
}